// round 11
// baseline (speedup 1.0000x reference)
#include <cuda_runtime.h>

// InteractionLayer: out[b, idx(i,j)] = dot(x[b,i,:], x[b,j,:]) for j > i
// x: [4096, 64, 128] fp32,  out: [4096, 2016] fp32
//
// Strategy (baseline, still unbenched — 11x broker timeouts):
//  - 2 batches per CTA, 288 threads (272 active compute lanes).
//  - Each active thread owns one 4x4 tile of the 16x16 tile grid; only the
//    136 upper-triangular tiles per batch are computed (halves the FMA work).
//  - x tiles staged in shared memory, [f][k] layout, float4-chunk XOR swizzle
//    (chunk = k4 ^ (f>>2)) -> coalesced global loads, conflict-free smem
//    writes AND conflict-free/broadcast LDS.128 reads in the compute loop.

#define NUM_F      64
#define NUM_D      128
#define B_TOTAL    4096
#define OUT_PER_B  2016
#define THREADS    288
#define ACTIVE     272
#define TILES      136          // 16*17/2 upper-triangular 4x4 tiles
#define BATCH_F4   2048         // 64 rows * 32 float4 per batch

__global__ __launch_bounds__(THREADS)
void interaction_kernel(const float* __restrict__ x, float* __restrict__ out) {
    extern __shared__ float4 s4[];          // 2 batches * 2048 float4 = 64 KB
    const int tid = threadIdx.x;
    const int b0  = blockIdx.x * 2;

    // ---- cooperative load of 2 batches into swizzled smem ----
    // global float4 index (bb, f, k4) = bb*2048 + f*32 + k4  (matches idx)
    const float4* g4 = reinterpret_cast<const float4*>(x) + (size_t)b0 * BATCH_F4;
    #pragma unroll
    for (int it = 0; it < 15; ++it) {       // ceil(4096 / 288) = 15
        int idx = it * THREADS + tid;
        if (idx < 2 * BATCH_F4) {
            int bb  = idx >> 11;            // / 2048
            int rem = idx & 2047;
            int f   = rem >> 5;             // row (feature)
            int k4  = rem & 31;             // float4 chunk along d
            s4[bb * BATCH_F4 + f * 32 + (k4 ^ (f >> 2))] = g4[idx];
        }
    }
    __syncthreads();

    if (tid < ACTIVE) {
        const int bb = (tid >= TILES) ? 1 : 0;
        const int t  = tid - bb * TILES;

        // decode linear tile index t -> (bi, bj) with bi <= bj, row-major
        int bi = 0, rem = t, cnt = 16;
        while (rem >= cnt) { rem -= cnt; ++bi; --cnt; }
        const int bj = bi + rem;

        const float4* sb = s4 + bb * BATCH_F4;
        const int i0 = 4 * bi, j0 = 4 * bj;

        float c00 = 0.f, c01 = 0.f, c02 = 0.f, c03 = 0.f;
        float c10 = 0.f, c11 = 0.f, c12 = 0.f, c13 = 0.f;
        float c20 = 0.f, c21 = 0.f, c22 = 0.f, c23 = 0.f;
        float c30 = 0.f, c31 = 0.f, c32 = 0.f, c33 = 0.f;

        #pragma unroll 8
        for (int k4 = 0; k4 < 32; ++k4) {
            const int swi = k4 ^ bi;        // swizzled chunk for i-rows
            const int swj = k4 ^ bj;        // swizzled chunk for j-rows
            float4 a0 = sb[(i0 + 0) * 32 + swi];
            float4 a1 = sb[(i0 + 1) * 32 + swi];
            float4 a2 = sb[(i0 + 2) * 32 + swi];
            float4 a3 = sb[(i0 + 3) * 32 + swi];
            float4 e0 = sb[(j0 + 0) * 32 + swj];
            float4 e1 = sb[(j0 + 1) * 32 + swj];
            float4 e2 = sb[(j0 + 2) * 32 + swj];
            float4 e3 = sb[(j0 + 3) * 32 + swj];

            c00 += a0.x*e0.x + a0.y*e0.y + a0.z*e0.z + a0.w*e0.w;
            c01 += a0.x*e1.x + a0.y*e1.y + a0.z*e1.z + a0.w*e1.w;
            c02 += a0.x*e2.x + a0.y*e2.y + a0.z*e2.z + a0.w*e2.w;
            c03 += a0.x*e3.x + a0.y*e3.y + a0.z*e3.z + a0.w*e3.w;
            c10 += a1.x*e0.x + a1.y*e0.y + a1.z*e0.z + a1.w*e0.w;
            c11 += a1.x*e1.x + a1.y*e1.y + a1.z*e1.z + a1.w*e1.w;
            c12 += a1.x*e2.x + a1.y*e2.y + a1.z*e2.z + a1.w*e2.w;
            c13 += a1.x*e3.x + a1.y*e3.y + a1.z*e3.z + a1.w*e3.w;
            c20 += a2.x*e0.x + a2.y*e0.y + a2.z*e0.z + a2.w*e0.w;
            c21 += a2.x*e1.x + a2.y*e1.y + a2.z*e1.z + a2.w*e1.w;
            c22 += a2.x*e2.x + a2.y*e2.y + a2.z*e2.z + a2.w*e2.w;
            c23 += a2.x*e3.x + a2.y*e3.y + a2.z*e3.z + a2.w*e3.w;
            c30 += a3.x*e0.x + a3.y*e0.y + a3.z*e0.z + a3.w*e0.w;
            c31 += a3.x*e1.x + a3.y*e1.y + a3.z*e1.z + a3.w*e1.w;
            c32 += a3.x*e2.x + a3.y*e2.y + a3.z*e2.z + a3.w*e2.w;
            c33 += a3.x*e3.x + a3.y*e3.y + a3.z*e3.z + a3.w*e3.w;
        }

        // ---- write strictly-upper-triangular entries ----
        // idx(i,j) = i*63 - i*(i-1)/2 + (j - i - 1)
        float* ob = out + (size_t)(b0 + bb) * OUT_PER_B;
        float cc[4][4] = {{c00,c01,c02,c03},{c10,c11,c12,c13},
                          {c20,c21,c22,c23},{c30,c31,c32,c33}};
        #pragma unroll
        for (int r = 0; r < 4; ++r) {
            const int i = i0 + r;
            const int base = i * 63 - (i * (i - 1)) / 2 - i - 1;  // + j
            #pragma unroll
            for (int s = 0; s < 4; ++s) {
                const int j = j0 + s;
                if (j > i) ob[base + j] = cc[r][s];
            }
        }
    }
}

extern "C" void kernel_launch(void* const* d_in, const int* in_sizes, int n_in,
                              void* d_out, int out_size) {
    (void)in_sizes; (void)n_in; (void)out_size;
    const float* x = (const float*)d_in[0];
    float* out = (float*)d_out;

    const int smem = 2 * BATCH_F4 * sizeof(float4);   // 64 KB dynamic smem
    // Idempotent, deterministic, capture-safe: set every call (no static guards).
    cudaFuncSetAttribute(interaction_kernel,
                         cudaFuncAttributeMaxDynamicSharedMemorySize, smem);
    interaction_kernel<<<B_TOTAL / 2, THREADS, smem>>>(x, out);
}